// round 4
// baseline (speedup 1.0000x reference)
#include <cuda_runtime.h>
#include <cstdint>

// Problem constants
#define NB    1024
#define NTCR  100
#define NFEAT 15
#define NAA   24
#define NCH   14          // total conv output channels
#define NINST (NB*NTCR)   // 102400
#define NPAIR (NINST/2)   // 51200  (two instances packed per f32x2 lane)
#define PAIRS_PER_BLOCK 8 // 4 warps * 2 pairs
#define NBLK_CONV (NPAIR/PAIRS_PER_BLOCK) // 6400
#define NWPACK 1484       // 1470 weights + 14 biases (packed f32x2)

// ---------------- scratch (static device memory; no allocation) ----------------
__device__ float2 g_hbuf[NPAIR * NCH];          // h vectors, packed (instA, instB)
__device__ float2 g_sbuf[NPAIR];                // attention scores, packed
__device__ float  g_zbuf[NB * NCH];             // decoder_f output (pre-BN)
__device__ unsigned long long g_wpack[NWPACK];  // staged packed conv weights+bias

// ---------------- helpers ----------------
__device__ __forceinline__ unsigned long long ffma2(unsigned long long a,
                                                    unsigned long long b,
                                                    unsigned long long c) {
    unsigned long long d;
    asm("fma.rn.f32x2 %0, %1, %2, %3;" : "=l"(d) : "l"(a), "l"(b), "l"(c));
    return d;
}
__device__ __forceinline__ float lo2(unsigned long long v) {
    return __uint_as_float((unsigned)(v & 0xffffffffull));
}
__device__ __forceinline__ float hi2(unsigned long long v) {
    return __uint_as_float((unsigned)(v >> 32));
}
__device__ __forceinline__ unsigned long long pack2(float a, float b) {
    return ((unsigned long long)__float_as_uint(b) << 32) | __float_as_uint(a);
}

// ---------------- prep: pack conv weights into staging buffer ----------------
__global__ void prepKernel(const float* __restrict__ w0, const float* __restrict__ b0,
                           const float* __restrict__ w1, const float* __restrict__ b1,
                           const float* __restrict__ w2, const float* __restrict__ b2,
                           const float* __restrict__ w3, const float* __restrict__ b3,
                           const float* __restrict__ w4, const float* __restrict__ b4,
                           const float* __restrict__ w5, const float* __restrict__ b5) {
    const int chH[14]    = {2,2,2,3,3,3,4,4,4,5,5,6,6,7};
    const int chF[14]    = {0,1,2,0,1,2,0,1,2,0,1,0,1,0};
    const int chConv[14] = {0,0,0,1,1,1,2,2,2,3,3,4,4,5};
    const float* cws[6] = {w0,w1,w2,w3,w4,w5};
    const float* cbs[6] = {b0,b1,b2,b3,b4,b5};
    int idx = blockIdx.x * blockDim.x + threadIdx.x;
    if (idx < 1470) {
        int ch = idx % 14;
        int r  = idx / 14;
        int t  = r % 7;
        int c  = r / 7;
        int h  = chH[ch];
        float w = 0.0f;
        if (t < h) {
            const float* W = cws[chConv[ch]];
            w = W[(chF[ch] * NFEAT + c) * h + t];
        }
        g_wpack[idx] = pack2(w, w);
    } else if (idx < NWPACK) {
        int ch = idx - 1470;
        float b = cbs[chConv[ch]][chF[ch]];
        g_wpack[idx] = pack2(b, b);
    }
}

// ---------------- stage 1: conv + relu + maxpool + fc1 + relu + score ----------------
__global__ void __launch_bounds__(128) convKernel(const float* __restrict__ x,
                                                  const float* __restrict__ fc1w,
                                                  const float* __restrict__ fc1b,
                                                  const float* __restrict__ waw) {
    __shared__ unsigned long long xs[4][2][452]; // [warp][pp][15 rows * stride30 + pad]
    __shared__ unsigned long long ws[NWPACK];    // conv weights (f32x2-duplicated)
    __shared__ float fcw[196];
    __shared__ float fcb[14];
    __shared__ float wav[14];

    int tid  = threadIdx.x;
    int w    = tid >> 5;
    int lane = tid & 31;

    // Weights come from GLOBAL->SHARED, not __constant__: the Blackwell
    // constant port (LDC floor 8, GPR dest) serialized the old version
    // (~1.3ms LDC-bound). Broadcast LDS.64 has no such bottleneck.
    for (int i = tid; i < NWPACK; i += 128) ws[i] = g_wpack[i];
    for (int i = tid; i < 196; i += 128) fcw[i] = fc1w[i];
    if (tid < 14)  { fcb[tid] = fc1b[tid]; wav[tid] = waw[tid]; }

    int pairBase = blockIdx.x * PAIRS_PER_BLOCK + w * 2;

    // zero-pad then fill x tiles (2 pairs = 4 instances, packed 2-wide)
    #pragma unroll
    for (int pp = 0; pp < 2; ++pp) {
        unsigned long long* xw = xs[w][pp];
        for (int i = lane; i < 452; i += 32) xw[i] = 0ull;
    }
    __syncwarp();
    #pragma unroll
    for (int pp = 0; pp < 2; ++pp) {
        const float* xg = x + (size_t)(pairBase + pp) * 720;
        unsigned long long* xw = xs[w][pp];
        for (int i = lane; i < 360; i += 32) {
            int c = i / 24;
            int a = i - c * 24;
            xw[c * 30 + a] = pack2(xg[i], xg[360 + i]);
        }
    }
    __syncthreads();

    int lp = (lane < 24) ? lane : 0;
    unsigned long long a0[14], a1[14];
    #pragma unroll
    for (int ch = 0; ch < 14; ++ch) { a0[ch] = 0ull; a1[ch] = 0ull; }

    const unsigned long long* x0 = xs[w][0] + lp;
    const unsigned long long* x1 = xs[w][1] + lp;
    constexpr int CS[7] = {0, 0, 3, 6, 9, 11, 13}; // first active channel per tap

    #pragma unroll 1
    for (int c = 0; c < 15; ++c) {
        const unsigned long long* wrow = ws + c * 98;
        #pragma unroll
        for (int t = 0; t < 7; ++t) {
            unsigned long long xv0 = x0[c * 30 + t];
            unsigned long long xv1 = x1[c * 30 + t];
            #pragma unroll
            for (int ch = CS[t]; ch < 14; ++ch) {
                unsigned long long wv = wrow[t * 14 + ch];
                a0[ch] = ffma2(wv, xv0, a0[ch]);
                a1[ch] = ffma2(wv, xv1, a1[ch]);
            }
        }
    }

    // bias + relu + masked global max over positions
    constexpr int chHt[14] = {2,2,2,3,3,3,4,4,4,5,5,6,6,7};
    float f0x[14], f0y[14], f1x[14], f1y[14];
    #pragma unroll
    for (int ch = 0; ch < 14; ++ch) {
        float bb  = lo2(ws[1470 + ch]);
        float vx0 = fmaxf(lo2(a0[ch]) + bb, 0.0f);
        float vy0 = fmaxf(hi2(a0[ch]) + bb, 0.0f);
        float vx1 = fmaxf(lo2(a1[ch]) + bb, 0.0f);
        float vy1 = fmaxf(hi2(a1[ch]) + bb, 0.0f);
        if (lane > 24 - chHt[ch]) { vx0 = 0.0f; vy0 = 0.0f; vx1 = 0.0f; vy1 = 0.0f; }
        #pragma unroll
        for (int off = 16; off; off >>= 1) {
            vx0 = fmaxf(vx0, __shfl_xor_sync(0xffffffffu, vx0, off));
            vy0 = fmaxf(vy0, __shfl_xor_sync(0xffffffffu, vy0, off));
            vx1 = fmaxf(vx1, __shfl_xor_sync(0xffffffffu, vx1, off));
            vy1 = fmaxf(vy1, __shfl_xor_sync(0xffffffffu, vy1, off));
        }
        f0x[ch] = vx0; f0y[ch] = vy0; f1x[ch] = vx1; f1y[ch] = vy1;
    }

    // fc1 + relu + attention score: lanes 0..13 -> pair pp0, lanes 16..29 -> pair pp1
    int g = lane >> 4;   // which pair
    int j = lane & 15;   // output dim
    float hx = 0.0f, hy = 0.0f;
    if (j < 14) { hx = fcb[j]; hy = fcb[j]; }
    #pragma unroll
    for (int k = 0; k < 14; ++k) {
        float fx = g ? f1x[k] : f0x[k];
        float fy = g ? f1y[k] : f0y[k];
        float ww = 0.0f;
        if (j < 14) ww = fcw[j * 14 + k];
        hx = fmaf(ww, fx, hx);
        hy = fmaf(ww, fy, hy);
    }
    hx = fmaxf(hx, 0.0f);
    hy = fmaxf(hy, 0.0f);
    float px = 0.0f, py = 0.0f;
    if (j < 14) { float wa = wav[j]; px = hx * wa; py = hy * wa; }
    #pragma unroll
    for (int off = 1; off < 16; off <<= 1) {
        px += __shfl_xor_sync(0xffffffffu, px, off);
        py += __shfl_xor_sync(0xffffffffu, py, off);
    }
    int pair = pairBase + g;
    if (j < 14) g_hbuf[pair * 14 + j] = make_float2(hx, hy);
    if (j == 0) g_sbuf[pair] = make_float2(px, py);
}

// ---------------- stage 2: sparsemax + pooled + decoder_f (one block per repertoire) ----------------
__global__ void __launch_bounds__(128) attnKernel(const float* __restrict__ decfw,
                                                  const float* __restrict__ decfb,
                                                  float* __restrict__ out,
                                                  int write_attw) {
    __shared__ float z[100];
    __shared__ float zsrt[100];
    __shared__ float aw[100];
    __shared__ float2 hsh[700];
    __shared__ float pooled[14];
    __shared__ float tau_s;

    int b = blockIdx.x;
    int t = threadIdx.x;

    if (t < 50) {
        float2 s2 = g_sbuf[b * 50 + t];
        z[2 * t]     = s2.x;
        z[2 * t + 1] = s2.y;
    }
    for (int i = t; i < 700; i += 128) hsh[i] = g_hbuf[b * 700 + i];
    __syncthreads();

    // exact O(n^2) rank sort (descending, stable)
    if (t < 100) {
        float zi = z[t];
        int r = 0;
        for (int j2 = 0; j2 < 100; ++j2) {
            float zj = z[j2];
            r += (int)(zj > zi) | ((int)(zj == zi) & (int)(j2 < t));
        }
        zsrt[r] = zi;
    }
    __syncthreads();

    if (t == 0) {
        float cs = 0.0f, cssel = 0.0f;
        int ks = 1;
        for (int i = 0; i < 100; ++i) {
            cs += zsrt[i];
            if (1.0f + (float)(i + 1) * zsrt[i] > cs) { ks = i + 1; cssel = cs; }
        }
        tau_s = (cssel - 1.0f) / (float)ks;
    }
    __syncthreads();

    float tau = tau_s;
    if (t < 100) {
        float a = fmaxf(z[t] - tau, 0.0f);
        aw[t] = a;
        // attw is only part of the harness output when out_size covers it;
        // writing it unconditionally would be OOB if output is logits-only.
        if (write_attw) out[2048 + b * 100 + t] = a;
    }
    __syncthreads();

    if (t < 14) {
        float acc = 0.0f;
        #pragma unroll 5
        for (int p = 0; p < 50; ++p) {
            float2 h2 = hsh[p * 14 + t];
            acc = fmaf(aw[2 * p],     h2.x, acc);
            acc = fmaf(aw[2 * p + 1], h2.y, acc);
        }
        pooled[t] = acc;
    }
    __syncthreads();

    if (t < 14) {
        float zz = decfb[t];
        #pragma unroll
        for (int k = 0; k < 14; ++k) zz = fmaf(decfw[t * 14 + k], pooled[k], zz);
        g_zbuf[b * 14 + t] = zz;
    }
}

// ---------------- stage 3: batchnorm (batch stats) + relu + decoder_s ----------------
__global__ void __launch_bounds__(1024) bnKernel(const float* __restrict__ bng,
                                                 const float* __restrict__ bnb,
                                                 const float* __restrict__ dsw,
                                                 const float* __restrict__ dsb,
                                                 float* __restrict__ out) {
    __shared__ float ssum[32][14];
    __shared__ float ssq[32][14];
    __shared__ float mu[14];
    __shared__ float sc[14];

    int b    = threadIdx.x;
    int w    = b >> 5;
    int lane = b & 31;

    float zr[14];
    #pragma unroll
    for (int j = 0; j < 14; ++j) zr[j] = g_zbuf[b * 14 + j];

    #pragma unroll
    for (int j = 0; j < 14; ++j) {
        float s = zr[j];
        float q = zr[j] * zr[j];
        #pragma unroll
        for (int off = 16; off; off >>= 1) {
            s += __shfl_xor_sync(0xffffffffu, s, off);
            q += __shfl_xor_sync(0xffffffffu, q, off);
        }
        if (lane == 0) { ssum[w][j] = s; ssq[w][j] = q; }
    }
    __syncthreads();

    if (b < 14) {
        float s = 0.0f, q = 0.0f;
        #pragma unroll
        for (int i = 0; i < 32; ++i) { s += ssum[i][b]; q += ssq[i][b]; }
        float m = s * (1.0f / 1024.0f);
        float v = q * (1.0f / 1024.0f) - m * m;
        mu[b] = m;
        sc[b] = bng[b] * rsqrtf(v + 1e-5f);
    }
    __syncthreads();

    float l0 = dsb[0], l1 = dsb[1];
    #pragma unroll
    for (int j = 0; j < 14; ++j) {
        float zn = fmaxf((zr[j] - mu[j]) * sc[j] + bnb[j], 0.0f);
        l0 = fmaf(dsw[j],      zn, l0);
        l1 = fmaf(dsw[14 + j], zn, l1);
    }
    out[b * 2]     = l0;
    out[b * 2 + 1] = l1;
}

// ---------------- launch ----------------
extern "C" void kernel_launch(void* const* d_in, const int* in_sizes, int n_in,
                              void* d_out, int out_size) {
    // Input index maps: insertion order (setup_inputs dict order) vs
    // alphabetized metadata. Detect via the unmistakable x element count.
    static const int MAP_INS[22] = {0,1,2,3,4,5,6,7,8,9,10,11,12,13,14,15,16,17,18,19,20,21};
    //                       x  cw0 cb0 cw1 cb1 cw2 cb2 cw3 cb3 cw4 cb4 cw5 cb5 f1w f1b waw dfw dfb bng bnb dsw dsb
    static const int MAP_AL[22] = {21, 8,  2,  9,  3, 10,  4, 11,  5, 12,  6, 13,  7, 19, 18, 20, 15, 14,  1,  0, 17, 16};

    const int* M = MAP_INS;
    if (n_in >= 22 && in_sizes[0] != NINST * NFEAT * NAA && in_sizes[21] == NINST * NFEAT * NAA) {
        M = MAP_AL;
    }

    const float* x    = (const float*)d_in[M[0]];
    const float* cw0  = (const float*)d_in[M[1]];
    const float* cb0  = (const float*)d_in[M[2]];
    const float* cw1  = (const float*)d_in[M[3]];
    const float* cb1  = (const float*)d_in[M[4]];
    const float* cw2  = (const float*)d_in[M[5]];
    const float* cb2  = (const float*)d_in[M[6]];
    const float* cw3  = (const float*)d_in[M[7]];
    const float* cb3  = (const float*)d_in[M[8]];
    const float* cw4  = (const float*)d_in[M[9]];
    const float* cb4  = (const float*)d_in[M[10]];
    const float* cw5  = (const float*)d_in[M[11]];
    const float* cb5  = (const float*)d_in[M[12]];
    const float* fc1w = (const float*)d_in[M[13]];
    const float* fc1b = (const float*)d_in[M[14]];
    const float* waw  = (const float*)d_in[M[15]];
    const float* dfw  = (const float*)d_in[M[16]];
    const float* dfb  = (const float*)d_in[M[17]];
    const float* bng  = (const float*)d_in[M[18]];
    const float* bnb  = (const float*)d_in[M[19]];
    const float* dsw  = (const float*)d_in[M[20]];
    const float* dsb  = (const float*)d_in[M[21]];
    float* out = (float*)d_out;

    // Only emit attw if the output buffer actually has room for it
    // (logits = 2048 floats, attw = 102400 floats).
    int write_attw = (out_size >= 2048 + NB * NTCR) ? 1 : 0;

    prepKernel<<<6, 256>>>(cw0, cb0, cw1, cb1, cw2, cb2, cw3, cb3, cw4, cb4, cw5, cb5);
    convKernel<<<NBLK_CONV, 128>>>(x, fc1w, fc1b, waw);
    attnKernel<<<NB, 128>>>(dfw, dfb, out, write_attw);
    bnKernel<<<1, 1024>>>(bng, bnb, dsw, dsb, out);
}

// round 5
// speedup vs baseline: 1.0111x; 1.0111x over previous
#include <cuda_runtime.h>
#include <cstdint>

// Problem constants
#define NB    1024
#define NTCR  100
#define NFEAT 15
#define NAA   24
#define NCH   14          // total conv output channels
#define NINST (NB*NTCR)   // 102400
#define INST_PER_BLOCK 16 // 4 warps * 4 instances
#define NBLK_CONV (NINST/INST_PER_BLOCK) // 6400
#define NWPACK 1484       // 1470 weights + 14 biases

// ---------------- scratch (static device memory; no allocation) ----------------
__device__ float g_hbuf[NINST * NCH];   // h vectors (per instance)
__device__ float g_sbuf[NINST];         // attention scores
__device__ float g_zbuf[NB * NCH];      // decoder_f output (pre-BN)
__device__ float g_wpack[NWPACK];       // staged conv weights+bias

// ---------------- prep: pack conv weights into staging buffer ----------------
__global__ void prepKernel(const float* __restrict__ w0, const float* __restrict__ b0,
                           const float* __restrict__ w1, const float* __restrict__ b1,
                           const float* __restrict__ w2, const float* __restrict__ b2,
                           const float* __restrict__ w3, const float* __restrict__ b3,
                           const float* __restrict__ w4, const float* __restrict__ b4,
                           const float* __restrict__ w5, const float* __restrict__ b5) {
    const int chH[14]    = {2,2,2,3,3,3,4,4,4,5,5,6,6,7};
    const int chF[14]    = {0,1,2,0,1,2,0,1,2,0,1,0,1,0};
    const int chConv[14] = {0,0,0,1,1,1,2,2,2,3,3,4,4,5};
    const float* cws[6] = {w0,w1,w2,w3,w4,w5};
    const float* cbs[6] = {b0,b1,b2,b3,b4,b5};
    int idx = blockIdx.x * blockDim.x + threadIdx.x;
    if (idx < 1470) {
        int ch = idx % 14;
        int r  = idx / 14;
        int t  = r % 7;
        int c  = r / 7;
        int h  = chH[ch];
        float w = 0.0f;
        if (t < h) {
            const float* W = cws[chConv[ch]];
            w = W[(chF[ch] * NFEAT + c) * h + t];
        }
        g_wpack[idx] = w;
    } else if (idx < NWPACK) {
        int ch = idx - 1470;
        g_wpack[idx] = cbs[chConv[ch]][chF[ch]];
    }
}

// ---------------- stage 1: conv + relu + maxpool + fc1 + relu + score ----------------
// Scalar FFMA version: fma.rn.f32x2 was the R3/R4 bottleneck (packed 64-bit FMA
// appears to run at FP64-class throughput on B300, ~18 cyc/SM reciprocal).
// warp = 4 instances, lane = conv output position (24 active).
__global__ void __launch_bounds__(128) convKernel(const float* __restrict__ x,
                                                  const float* __restrict__ fc1w,
                                                  const float* __restrict__ fc1b,
                                                  const float* __restrict__ waw) {
    __shared__ float xs[4][4][452]; // [warp][inst][15 rows * stride30 + pad]
    __shared__ float ws[NWPACK];    // conv weights + biases
    __shared__ float fcw[196];
    __shared__ float fcb[16];
    __shared__ float wav[16];

    int tid  = threadIdx.x;
    int w    = tid >> 5;
    int lane = tid & 31;

    for (int i = tid; i < NWPACK; i += 128) ws[i] = g_wpack[i];
    for (int i = tid; i < 196; i += 128) fcw[i] = fc1w[i];
    if (tid < 16) {
        fcb[tid] = (tid < 14) ? fc1b[tid] : 0.0f;
        wav[tid] = (tid < 14) ? waw[tid]  : 0.0f;
    }

    int instBase = blockIdx.x * INST_PER_BLOCK + w * 4;

    // zero-pad then fill x tiles (4 instances per warp)
    float* xw = &xs[w][0][0];
    for (int i = lane; i < 4 * 452; i += 32) xw[i] = 0.0f;
    __syncwarp();
    {
        const float* xg = x + (size_t)instBase * 360;
        for (int i = lane; i < 4 * 360; i += 32) {
            int inst = i / 360;
            int r    = i - inst * 360;
            int c    = r / 24;
            int a    = r - c * 24;
            xs[w][inst][c * 30 + a] = xg[i];
        }
    }
    __syncthreads();

    int lp = (lane < 24) ? lane : 0;
    float a0[14], a1[14], a2[14], a3[14];
    #pragma unroll
    for (int ch = 0; ch < 14; ++ch) { a0[ch] = 0.f; a1[ch] = 0.f; a2[ch] = 0.f; a3[ch] = 0.f; }

    constexpr int CS[7] = {0, 0, 3, 6, 9, 11, 13}; // first active channel per tap

    #pragma unroll 1
    for (int c = 0; c < 15; ++c) {
        const float* wrow = ws + c * 98;
        const float* xr0 = &xs[w][0][c * 30 + lp];
        const float* xr1 = &xs[w][1][c * 30 + lp];
        const float* xr2 = &xs[w][2][c * 30 + lp];
        const float* xr3 = &xs[w][3][c * 30 + lp];
        #pragma unroll
        for (int t = 0; t < 7; ++t) {
            float xv0 = xr0[t];
            float xv1 = xr1[t];
            float xv2 = xr2[t];
            float xv3 = xr3[t];
            #pragma unroll
            for (int ch = CS[t]; ch < 14; ++ch) {
                float wv = wrow[t * 14 + ch];
                a0[ch] = fmaf(wv, xv0, a0[ch]);
                a1[ch] = fmaf(wv, xv1, a1[ch]);
                a2[ch] = fmaf(wv, xv2, a2[ch]);
                a3[ch] = fmaf(wv, xv3, a3[ch]);
            }
        }
    }

    // bias + relu + masked global max over positions (result broadcast to all lanes)
    constexpr int chHt[14] = {2,2,2,3,3,3,4,4,4,5,5,6,6,7};
    #pragma unroll
    for (int ch = 0; ch < 14; ++ch) {
        float bb = ws[1470 + ch];
        float v0 = fmaxf(a0[ch] + bb, 0.0f);
        float v1 = fmaxf(a1[ch] + bb, 0.0f);
        float v2 = fmaxf(a2[ch] + bb, 0.0f);
        float v3 = fmaxf(a3[ch] + bb, 0.0f);
        if (lane > 24 - chHt[ch]) { v0 = 0.f; v1 = 0.f; v2 = 0.f; v3 = 0.f; }
        #pragma unroll
        for (int off = 16; off; off >>= 1) {
            v0 = fmaxf(v0, __shfl_xor_sync(0xffffffffu, v0, off));
            v1 = fmaxf(v1, __shfl_xor_sync(0xffffffffu, v1, off));
            v2 = fmaxf(v2, __shfl_xor_sync(0xffffffffu, v2, off));
            v3 = fmaxf(v3, __shfl_xor_sync(0xffffffffu, v3, off));
        }
        a0[ch] = v0; a1[ch] = v1; a2[ch] = v2; a3[ch] = v3;
    }

    // fc1 + relu + attention score. Two passes: pass g handles instances
    // 2g+{0,1}; lanes 0-15 -> sub 0, lanes 16-31 -> sub 1; j = lane&15.
    int sub = lane >> 4;
    int j   = lane & 15;
    #pragma unroll
    for (int g = 0; g < 2; ++g) {
        float h = fcb[j]; // 0 for j>=14
        #pragma unroll
        for (int k = 0; k < 14; ++k) {
            float fA = (g == 0) ? a0[k] : a2[k];
            float fB = (g == 0) ? a1[k] : a3[k];
            float fv = sub ? fB : fA;
            float ww = (j < 14) ? fcw[j * 14 + k] : 0.0f;
            h = fmaf(ww, fv, h);
        }
        h = fmaxf(h, 0.0f);
        float p = h * wav[j]; // 0 for j>=14
        #pragma unroll
        for (int off = 1; off < 16; off <<= 1)
            p += __shfl_xor_sync(0xffffffffu, p, off);
        int inst = instBase + 2 * g + sub;
        if (j < 14) g_hbuf[inst * 14 + j] = h;
        if (j == 0) g_sbuf[inst] = p;
    }
}

// ---------------- stage 2: sparsemax + pooled + decoder_f (one block per repertoire) ----------------
__global__ void __launch_bounds__(128) attnKernel(const float* __restrict__ decfw,
                                                  const float* __restrict__ decfb,
                                                  float* __restrict__ out,
                                                  int write_attw) {
    __shared__ float z[100];
    __shared__ float zsrt[100];
    __shared__ float aw[100];
    __shared__ float hsh[1400];
    __shared__ float pooled[14];
    __shared__ float tau_s;

    int b = blockIdx.x;
    int t = threadIdx.x;

    if (t < 100) z[t] = g_sbuf[b * 100 + t];
    for (int i = t; i < 1400; i += 128) hsh[i] = g_hbuf[b * 1400 + i];
    __syncthreads();

    // exact O(n^2) rank sort (descending, stable)
    if (t < 100) {
        float zi = z[t];
        int r = 0;
        for (int j2 = 0; j2 < 100; ++j2) {
            float zj = z[j2];
            r += (int)(zj > zi) | ((int)(zj == zi) & (int)(j2 < t));
        }
        zsrt[r] = zi;
    }
    __syncthreads();

    if (t == 0) {
        float cs = 0.0f, cssel = 0.0f;
        int ks = 1;
        for (int i = 0; i < 100; ++i) {
            cs += zsrt[i];
            if (1.0f + (float)(i + 1) * zsrt[i] > cs) { ks = i + 1; cssel = cs; }
        }
        tau_s = (cssel - 1.0f) / (float)ks;
    }
    __syncthreads();

    float tau = tau_s;
    if (t < 100) {
        float a = fmaxf(z[t] - tau, 0.0f);
        aw[t] = a;
        // attw only emitted when the output buffer has room (OOB-safe).
        if (write_attw) out[2048 + b * 100 + t] = a;
    }
    __syncthreads();

    if (t < 14) {
        float acc = 0.0f;
        #pragma unroll 4
        for (int p = 0; p < 100; ++p)
            acc = fmaf(aw[p], hsh[p * 14 + t], acc);
        pooled[t] = acc;
    }
    __syncthreads();

    if (t < 14) {
        float zz = decfb[t];
        #pragma unroll
        for (int k = 0; k < 14; ++k) zz = fmaf(decfw[t * 14 + k], pooled[k], zz);
        g_zbuf[b * 14 + t] = zz;
    }
}

// ---------------- stage 3: batchnorm (batch stats) + relu + decoder_s ----------------
__global__ void __launch_bounds__(1024) bnKernel(const float* __restrict__ bng,
                                                 const float* __restrict__ bnb,
                                                 const float* __restrict__ dsw,
                                                 const float* __restrict__ dsb,
                                                 float* __restrict__ out) {
    __shared__ float ssum[32][14];
    __shared__ float ssq[32][14];
    __shared__ float mu[14];
    __shared__ float sc[14];

    int b    = threadIdx.x;
    int w    = b >> 5;
    int lane = b & 31;

    float zr[14];
    #pragma unroll
    for (int j = 0; j < 14; ++j) zr[j] = g_zbuf[b * 14 + j];

    #pragma unroll
    for (int j = 0; j < 14; ++j) {
        float s = zr[j];
        float q = zr[j] * zr[j];
        #pragma unroll
        for (int off = 16; off; off >>= 1) {
            s += __shfl_xor_sync(0xffffffffu, s, off);
            q += __shfl_xor_sync(0xffffffffu, q, off);
        }
        if (lane == 0) { ssum[w][j] = s; ssq[w][j] = q; }
    }
    __syncthreads();

    if (b < 14) {
        float s = 0.0f, q = 0.0f;
        #pragma unroll
        for (int i = 0; i < 32; ++i) { s += ssum[i][b]; q += ssq[i][b]; }
        float m = s * (1.0f / 1024.0f);
        float v = q * (1.0f / 1024.0f) - m * m;
        mu[b] = m;
        sc[b] = bng[b] * rsqrtf(v + 1e-5f);
    }
    __syncthreads();

    float l0 = dsb[0], l1 = dsb[1];
    #pragma unroll
    for (int j = 0; j < 14; ++j) {
        float zn = fmaxf((zr[j] - mu[j]) * sc[j] + bnb[j], 0.0f);
        l0 = fmaf(dsw[j],      zn, l0);
        l1 = fmaf(dsw[14 + j], zn, l1);
    }
    out[b * 2]     = l0;
    out[b * 2 + 1] = l1;
}

// ---------------- launch ----------------
extern "C" void kernel_launch(void* const* d_in, const int* in_sizes, int n_in,
                              void* d_out, int out_size) {
    static const int MAP_INS[22] = {0,1,2,3,4,5,6,7,8,9,10,11,12,13,14,15,16,17,18,19,20,21};
    //                       x  cw0 cb0 cw1 cb1 cw2 cb2 cw3 cb3 cw4 cb4 cw5 cb5 f1w f1b waw dfw dfb bng bnb dsw dsb
    static const int MAP_AL[22] = {21, 8,  2,  9,  3, 10,  4, 11,  5, 12,  6, 13,  7, 19, 18, 20, 15, 14,  1,  0, 17, 16};

    const int* M = MAP_INS;
    if (n_in >= 22 && in_sizes[0] != NINST * NFEAT * NAA && in_sizes[21] == NINST * NFEAT * NAA) {
        M = MAP_AL;
    }

    const float* x    = (const float*)d_in[M[0]];
    const float* cw0  = (const float*)d_in[M[1]];
    const float* cb0  = (const float*)d_in[M[2]];
    const float* cw1  = (const float*)d_in[M[3]];
    const float* cb1  = (const float*)d_in[M[4]];
    const float* cw2  = (const float*)d_in[M[5]];
    const float* cb2  = (const float*)d_in[M[6]];
    const float* cw3  = (const float*)d_in[M[7]];
    const float* cb3  = (const float*)d_in[M[8]];
    const float* cw4  = (const float*)d_in[M[9]];
    const float* cb4  = (const float*)d_in[M[10]];
    const float* cw5  = (const float*)d_in[M[11]];
    const float* cb5  = (const float*)d_in[M[12]];
    const float* fc1w = (const float*)d_in[M[13]];
    const float* fc1b = (const float*)d_in[M[14]];
    const float* waw  = (const float*)d_in[M[15]];
    const float* dfw  = (const float*)d_in[M[16]];
    const float* dfb  = (const float*)d_in[M[17]];
    const float* bng  = (const float*)d_in[M[18]];
    const float* bnb  = (const float*)d_in[M[19]];
    const float* dsw  = (const float*)d_in[M[20]];
    const float* dsb  = (const float*)d_in[M[21]];
    float* out = (float*)d_out;

    int write_attw = (out_size >= 2048 + NB * NTCR) ? 1 : 0;

    prepKernel<<<6, 256>>>(cw0, cb0, cw1, cb1, cw2, cb2, cw3, cb3, cw4, cb4, cw5, cb5);
    convKernel<<<NBLK_CONV, 128>>>(x, fc1w, fc1b, waw);
    attnKernel<<<NB, 128>>>(dfw, dfb, out, write_attw);
    bnKernel<<<1, 1024>>>(bng, bnb, dsw, dsb, out);
}

// round 6
// speedup vs baseline: 1.1616x; 1.1488x over previous
#include <cuda_runtime.h>
#include <cstdint>

// Problem constants
#define NB    1024
#define NTCR  100
#define NFEAT 15
#define NAA   24
#define NCH   14          // total conv output channels
#define NINST (NB*NTCR)   // 102400
#define INST_PER_BLOCK 16 // 8 warps * 2 instances
#define NBLK_CONV (NINST/INST_PER_BLOCK) // 6400
#define NWPACK 1484       // 1470 weights + 14 biases

// ---------------- scratch (static device memory; no allocation) ----------------
__device__ float g_hbuf[NINST * NCH];   // h vectors (per instance)
__device__ float g_sbuf[NINST];         // attention scores
__device__ float g_zbuf[NB * NCH];      // decoder_f output (pre-BN)
__device__ float g_wpack[NWPACK];       // staged conv weights+bias

// ---------------- prep: pack conv weights into staging buffer ----------------
__global__ void prepKernel(const float* __restrict__ w0, const float* __restrict__ b0,
                           const float* __restrict__ w1, const float* __restrict__ b1,
                           const float* __restrict__ w2, const float* __restrict__ b2,
                           const float* __restrict__ w3, const float* __restrict__ b3,
                           const float* __restrict__ w4, const float* __restrict__ b4,
                           const float* __restrict__ w5, const float* __restrict__ b5) {
    const int chH[14]    = {2,2,2,3,3,3,4,4,4,5,5,6,6,7};
    const int chF[14]    = {0,1,2,0,1,2,0,1,2,0,1,0,1,0};
    const int chConv[14] = {0,0,0,1,1,1,2,2,2,3,3,4,4,5};
    const float* cws[6] = {w0,w1,w2,w3,w4,w5};
    const float* cbs[6] = {b0,b1,b2,b3,b4,b5};
    int idx = blockIdx.x * blockDim.x + threadIdx.x;
    if (idx < 1470) {
        int ch = idx % 14;
        int r  = idx / 14;
        int t  = r % 7;
        int c  = r / 7;
        int h  = chH[ch];
        float w = 0.0f;
        if (t < h) {
            const float* W = cws[chConv[ch]];
            w = W[(chF[ch] * NFEAT + c) * h + t];
        }
        g_wpack[idx] = w;
    } else if (idx < NWPACK) {
        int ch = idx - 1470;
        g_wpack[idx] = cbs[chConv[ch]][chF[ch]];
    }
}

// ---------------- stage 1: conv + relu + maxpool + fc1 + relu + score ----------------
// x lives in REGISTERS (coalesced LDG + shuffle for taps) — no x smem tile.
// smem = 6.9 KB/block -> many blocks/SM; 2 instances/warp -> ~60 regs ->
// ~8 warps/SMSP to hide LDS/LDG latency (the R3-R5 bottleneck hypothesis).
__global__ void __launch_bounds__(256) convKernel(const float* __restrict__ x,
                                                  const float* __restrict__ fc1w,
                                                  const float* __restrict__ fc1b,
                                                  const float* __restrict__ waw) {
    __shared__ float ws[NWPACK];    // conv weights + biases
    __shared__ float fcw[196];
    __shared__ float fcb[16];
    __shared__ float wav[16];

    int tid  = threadIdx.x;
    int w    = tid >> 5;
    int lane = tid & 31;

    for (int i = tid; i < NWPACK; i += 256) ws[i] = g_wpack[i];
    if (tid < 196) fcw[tid] = fc1w[tid];
    if (tid < 16) {
        fcb[tid] = (tid < 14) ? fc1b[tid] : 0.0f;
        wav[tid] = (tid < 14) ? waw[tid]  : 0.0f;
    }
    __syncthreads();

    int instBase = blockIdx.x * INST_PER_BLOCK + w * 2;
    const float* xg0 = x + (size_t)instBase * 360;
    const float* xg1 = xg0 + 360;

    float a0[14], a1[14];
    #pragma unroll
    for (int ch = 0; ch < 14; ++ch) { a0[ch] = 0.f; a1[ch] = 0.f; }

    constexpr int CS[7] = {0, 0, 3, 6, 9, 11, 13}; // first active channel per tap

    bool act = (lane < 24);
    float nx0 = act ? xg0[lane] : 0.0f;   // prefetch row c=0
    float nx1 = act ? xg1[lane] : 0.0f;

    #pragma unroll 1
    for (int c = 0; c < 15; ++c) {
        float xv0 = nx0, xv1 = nx1;
        if (c < 14) {   // prefetch next row (double-buffer in regs)
            nx0 = act ? xg0[(c + 1) * 24 + lane] : 0.0f;
            nx1 = act ? xg1[(c + 1) * 24 + lane] : 0.0f;
        }
        const float* wrow = ws + c * 98;
        #pragma unroll
        for (int t = 0; t < 7; ++t) {
            int src = lane + t; src = (src > 31) ? 31 : src;
            float xt0 = __shfl_sync(0xffffffffu, xv0, src);
            float xt1 = __shfl_sync(0xffffffffu, xv1, src);
            #pragma unroll
            for (int ch = CS[t]; ch < 14; ++ch) {
                float wv = wrow[t * 14 + ch];
                a0[ch] = fmaf(wv, xt0, a0[ch]);
                a1[ch] = fmaf(wv, xt1, a1[ch]);
            }
        }
    }

    // bias + relu + masked global max over positions (broadcast to all lanes)
    constexpr int chHt[14] = {2,2,2,3,3,3,4,4,4,5,5,6,6,7};
    #pragma unroll
    for (int ch = 0; ch < 14; ++ch) {
        float bb = ws[1470 + ch];
        float v0 = fmaxf(a0[ch] + bb, 0.0f);
        float v1 = fmaxf(a1[ch] + bb, 0.0f);
        if (lane > 24 - chHt[ch]) { v0 = 0.f; v1 = 0.f; }
        #pragma unroll
        for (int off = 16; off; off >>= 1) {
            v0 = fmaxf(v0, __shfl_xor_sync(0xffffffffu, v0, off));
            v1 = fmaxf(v1, __shfl_xor_sync(0xffffffffu, v1, off));
        }
        a0[ch] = v0; a1[ch] = v1;
    }

    // fc1 + relu + attention score: lanes 0-15 -> inst0, 16-31 -> inst1; j = lane&15
    int sub = lane >> 4;
    int j   = lane & 15;
    float h = fcb[j]; // 0 for j>=14
    #pragma unroll
    for (int k = 0; k < 14; ++k) {
        float fv = sub ? a1[k] : a0[k];
        float ww = (j < 14) ? fcw[j * 14 + k] : 0.0f;
        h = fmaf(ww, fv, h);
    }
    h = fmaxf(h, 0.0f);
    float p = h * wav[j]; // 0 for j>=14
    #pragma unroll
    for (int off = 1; off < 16; off <<= 1)
        p += __shfl_xor_sync(0xffffffffu, p, off);
    int inst = instBase + sub;
    if (j < 14) g_hbuf[inst * 14 + j] = h;
    if (j == 0) g_sbuf[inst] = p;
}

// ---------------- stage 2: sparsemax + pooled + decoder_f (one block per repertoire) ----------------
__global__ void __launch_bounds__(128) attnKernel(const float* __restrict__ decfw,
                                                  const float* __restrict__ decfb,
                                                  float* __restrict__ out,
                                                  int write_attw) {
    __shared__ float z[100];
    __shared__ float zsrt[100];
    __shared__ float csh[100];
    __shared__ float aw[100];
    __shared__ float hsh[1400];
    __shared__ float pooled[14];
    __shared__ int   ks_sh;

    int b = blockIdx.x;
    int t = threadIdx.x;

    if (t == 0) ks_sh = 1;
    if (t < 100) z[t] = g_sbuf[b * 100 + t];
    for (int i = t; i < 1400; i += 128) hsh[i] = g_hbuf[b * 1400 + i];
    __syncthreads();

    // exact O(n^2) rank sort (descending, stable)
    if (t < 100) {
        float zi = z[t];
        int r = 0;
        for (int j2 = 0; j2 < 100; ++j2) {
            float zj = z[j2];
            r += (int)(zj > zi) | ((int)(zj == zi) & (int)(j2 < t));
        }
        zsrt[r] = zi;
    }
    __syncthreads();

    // parallel cumsum (triangular) + support-size via atomicMax
    if (t < 100) {
        float cs = 0.0f;
        for (int i2 = 0; i2 <= t; ++i2) cs += zsrt[i2];
        csh[t] = cs;
        if (1.0f + (float)(t + 1) * zsrt[t] > cs) atomicMax(&ks_sh, t + 1);
    }
    __syncthreads();

    int   ks  = ks_sh;
    float tau = (csh[ks - 1] - 1.0f) / (float)ks;

    if (t < 100) {
        float a = fmaxf(z[t] - tau, 0.0f);
        aw[t] = a;
        // attw only emitted when the output buffer has room (OOB-safe).
        if (write_attw) out[2048 + b * 100 + t] = a;
    }
    __syncthreads();

    if (t < 14) {
        float acc = 0.0f;
        #pragma unroll 4
        for (int p = 0; p < 100; ++p)
            acc = fmaf(aw[p], hsh[p * 14 + t], acc);
        pooled[t] = acc;
    }
    __syncthreads();

    if (t < 14) {
        float zz = decfb[t];
        #pragma unroll
        for (int k = 0; k < 14; ++k) zz = fmaf(decfw[t * 14 + k], pooled[k], zz);
        g_zbuf[b * 14 + t] = zz;
    }
}

// ---------------- stage 3: batchnorm (batch stats) + relu + decoder_s ----------------
__global__ void __launch_bounds__(1024) bnKernel(const float* __restrict__ bng,
                                                 const float* __restrict__ bnb,
                                                 const float* __restrict__ dsw,
                                                 const float* __restrict__ dsb,
                                                 float* __restrict__ out) {
    __shared__ float ssum[32][14];
    __shared__ float ssq[32][14];
    __shared__ float mu[14];
    __shared__ float sc[14];

    int b    = threadIdx.x;
    int w    = b >> 5;
    int lane = b & 31;

    float zr[14];
    #pragma unroll
    for (int j = 0; j < 14; ++j) zr[j] = g_zbuf[b * 14 + j];

    #pragma unroll
    for (int j = 0; j < 14; ++j) {
        float s = zr[j];
        float q = zr[j] * zr[j];
        #pragma unroll
        for (int off = 16; off; off >>= 1) {
            s += __shfl_xor_sync(0xffffffffu, s, off);
            q += __shfl_xor_sync(0xffffffffu, q, off);
        }
        if (lane == 0) { ssum[w][j] = s; ssq[w][j] = q; }
    }
    __syncthreads();

    if (b < 14) {
        float s = 0.0f, q = 0.0f;
        #pragma unroll
        for (int i = 0; i < 32; ++i) { s += ssum[i][b]; q += ssq[i][b]; }
        float m = s * (1.0f / 1024.0f);
        float v = q * (1.0f / 1024.0f) - m * m;
        mu[b] = m;
        sc[b] = bng[b] * rsqrtf(v + 1e-5f);
    }
    __syncthreads();

    float l0 = dsb[0], l1 = dsb[1];
    #pragma unroll
    for (int j = 0; j < 14; ++j) {
        float zn = fmaxf((zr[j] - mu[j]) * sc[j] + bnb[j], 0.0f);
        l0 = fmaf(dsw[j],      zn, l0);
        l1 = fmaf(dsw[14 + j], zn, l1);
    }
    out[b * 2]     = l0;
    out[b * 2 + 1] = l1;
}

// ---------------- launch ----------------
extern "C" void kernel_launch(void* const* d_in, const int* in_sizes, int n_in,
                              void* d_out, int out_size) {
    static const int MAP_INS[22] = {0,1,2,3,4,5,6,7,8,9,10,11,12,13,14,15,16,17,18,19,20,21};
    //                       x  cw0 cb0 cw1 cb1 cw2 cb2 cw3 cb3 cw4 cb4 cw5 cb5 f1w f1b waw dfw dfb bng bnb dsw dsb
    static const int MAP_AL[22] = {21, 8,  2,  9,  3, 10,  4, 11,  5, 12,  6, 13,  7, 19, 18, 20, 15, 14,  1,  0, 17, 16};

    const int* M = MAP_INS;
    if (n_in >= 22 && in_sizes[0] != NINST * NFEAT * NAA && in_sizes[21] == NINST * NFEAT * NAA) {
        M = MAP_AL;
    }

    const float* x    = (const float*)d_in[M[0]];
    const float* cw0  = (const float*)d_in[M[1]];
    const float* cb0  = (const float*)d_in[M[2]];
    const float* cw1  = (const float*)d_in[M[3]];
    const float* cb1  = (const float*)d_in[M[4]];
    const float* cw2  = (const float*)d_in[M[5]];
    const float* cb2  = (const float*)d_in[M[6]];
    const float* cw3  = (const float*)d_in[M[7]];
    const float* cb3  = (const float*)d_in[M[8]];
    const float* cw4  = (const float*)d_in[M[9]];
    const float* cb4  = (const float*)d_in[M[10]];
    const float* cw5  = (const float*)d_in[M[11]];
    const float* cb5  = (const float*)d_in[M[12]];
    const float* fc1w = (const float*)d_in[M[13]];
    const float* fc1b = (const float*)d_in[M[14]];
    const float* waw  = (const float*)d_in[M[15]];
    const float* dfw  = (const float*)d_in[M[16]];
    const float* dfb  = (const float*)d_in[M[17]];
    const float* bng  = (const float*)d_in[M[18]];
    const float* bnb  = (const float*)d_in[M[19]];
    const float* dsw  = (const float*)d_in[M[20]];
    const float* dsb  = (const float*)d_in[M[21]];
    float* out = (float*)d_out;

    int write_attw = (out_size >= 2048 + NB * NTCR) ? 1 : 0;

    prepKernel<<<6, 256>>>(cw0, cb0, cw1, cb1, cw2, cb2, cw3, cb3, cw4, cb4, cw5, cb5);
    convKernel<<<NBLK_CONV, 256>>>(x, fc1w, fc1b, waw);
    attnKernel<<<NB, 128>>>(dfw, dfb, out, write_attw);
    bnKernel<<<1, 1024>>>(bng, bnb, dsw, dsb, out);
}